// round 1
// baseline (speedup 1.0000x reference)
#include <cuda_runtime.h>

// Problem constants
#define Bn 16
#define Tn 2048
#define Cn 1024
#define Hn 64

// Scratch for Q, K, V projections (8 MB each). Static __device__ arrays:
// the only legal scratch under the harness allocation guards.
__device__ float g_q[Bn * Tn * Hn];
__device__ float g_k[Bn * Tn * Hn];
__device__ float g_v[Bn * Tn * Hn];

// ---------------- packed f32x2 helpers (sm_103a) ----------------
__device__ __forceinline__ unsigned long long pk2(float x, float y) {
    unsigned long long r;
    asm("mov.b64 %0, {%1, %2};" : "=l"(r) : "f"(x), "f"(y));
    return r;
}
__device__ __forceinline__ void upk2(unsigned long long v, float& x, float& y) {
    asm("mov.b64 {%0, %1}, %2;" : "=f"(x), "=f"(y) : "l"(v));
}
#define FMA2(d, a, b) \
    asm("fma.rn.f32x2 %0, %1, %2, %0;" : "+l"(d) : "l"(a), "l"(b))
#define MUL2(d, a, b) \
    asm("mul.rn.f32x2 %0, %1, %2;" : "=l"(d) : "l"(a), "l"(b))

// ================= Kernel 1: QKV projection =================
// grid = (M/64, 3), block = 256. Each block: 64 rows x 64 cols of one of q/k/v.
__global__ __launch_bounds__(256) void qkv_kernel(
    const float* __restrict__ x,
    const float* __restrict__ wq,
    const float* __restrict__ wk,
    const float* __restrict__ wv)
{
    __shared__ __align__(16) float Xs[64 * 33];  // [m][k], pad 33 -> conflict-free
    __shared__ __align__(16) float Ws[32 * 64];  // [k][h]

    const int which = blockIdx.y;
    const float* w = (which == 0) ? wq : (which == 1) ? wk : wv;
    float* out = (which == 0) ? g_q : (which == 1) ? g_k : g_v;

    const int m0 = blockIdx.x * 64;
    const int tid = threadIdx.x;
    const int ty = tid >> 4;   // 0..15
    const int tx = tid & 15;   // 0..15

    unsigned long long acc[4][2];
#pragma unroll
    for (int i = 0; i < 4; i++) { acc[i][0] = 0ull; acc[i][1] = 0ull; }

    for (int kt = 0; kt < Cn / 32; kt++) {
        // Fill Xs: 64 rows x 32 k (coalesced float4 global reads)
#pragma unroll
        for (int l = 0; l < 2; l++) {
            int e = tid + l * 256;            // 0..511
            int row = e >> 3;                 // 0..63
            int c4 = (e & 7) << 2;            // 0..28
            float4 v = *(const float4*)&x[(size_t)(m0 + row) * Cn + kt * 32 + c4];
            Xs[row * 33 + c4 + 0] = v.x;
            Xs[row * 33 + c4 + 1] = v.y;
            Xs[row * 33 + c4 + 2] = v.z;
            Xs[row * 33 + c4 + 3] = v.w;
        }
        // Fill Ws: 32 k x 64 h (coalesced, natural layout)
#pragma unroll
        for (int l = 0; l < 2; l++) {
            int e = tid + l * 256;
            int row = e >> 4;                 // 0..31
            int c4 = (e & 15) << 2;           // 0..60
            *(float4*)&Ws[row * 64 + c4] =
                *(const float4*)&w[(size_t)(kt * 32 + row) * Hn + c4];
        }
        __syncthreads();

#pragma unroll
        for (int k = 0; k < 32; k++) {
            ulonglong2 bb = *(const ulonglong2*)&Ws[k * 64 + tx * 4];
#pragma unroll
            for (int i = 0; i < 4; i++) {
                float a = Xs[(ty * 4 + i) * 33 + k];
                unsigned long long a2 = pk2(a, a);
                FMA2(acc[i][0], a2, bb.x);
                FMA2(acc[i][1], a2, bb.y);
            }
        }
        __syncthreads();
    }

#pragma unroll
    for (int i = 0; i < 4; i++) {
        float4 v;
        upk2(acc[i][0], v.x, v.y);
        upk2(acc[i][1], v.z, v.w);
        *(float4*)&out[(size_t)(m0 + ty * 4 + i) * Hn + tx * 4] = v;
    }
}

// ================= Kernel 2: flash attention =================
// grid = (T/64, B), block = 256 (ty 16 x tx 16, 4x4 microtile).
// SMEM: QsT, KPs (K^T then P^T, aliased), Vs -> exactly 48 KB.
// XOR swizzle: element (row h/s, col c) stored at col (c ^ ((row>>2 & 7)<<2)).
__global__ __launch_bounds__(256) void attn_kernel(float* __restrict__ out)
{
    __shared__ __align__(16) float QsT[64 * 64];  // [h][r] swizzled
    __shared__ __align__(16) float KPs[64 * 64];  // [h][c] K^T swizzled, later [s][r] P^T swizzled
    __shared__ __align__(16) float Vs[64 * 64];   // [s][h] natural

    const int b = blockIdx.y;
    const int qt = (gridDim.x - 1) - blockIdx.x;  // heavy q-tiles scheduled first
    const int q0 = qt * 64;
    const int tid = threadIdx.x;
    const int ty = tid >> 4;
    const int tx = tid & 15;

    // Fill QsT (swizzled), fold in softmax scale H^-0.5 = 0.125
    const float scale = 0.125f;
#pragma unroll
    for (int l = 0; l < 4; l++) {
        int e = tid + l * 256;       // 0..1023
        int r = e >> 4;              // query row 0..63
        int h4 = e & 15;
        float4 v = *(const float4*)&g_q[((size_t)b * Tn + q0 + r) * Hn + h4 * 4];
        int pc = r ^ ((h4 & 7) << 2);
        QsT[(h4 * 4 + 0) * 64 + pc] = v.x * scale;
        QsT[(h4 * 4 + 1) * 64 + pc] = v.y * scale;
        QsT[(h4 * 4 + 2) * 64 + pc] = v.z * scale;
        QsT[(h4 * 4 + 3) * 64 + pc] = v.w * scale;
    }

    float m_i[4], l_i[4];
    unsigned long long o2[4][2];
#pragma unroll
    for (int i = 0; i < 4; i++) {
        m_i[i] = -1e30f; l_i[i] = 0.f; o2[i][0] = 0ull; o2[i][1] = 0ull;
    }

    for (int st = 0; st <= qt; st++) {
        const int s0 = st * 64;
        __syncthreads();  // prior-iter reads (and QsT fill) complete before refilling

        // Fill KsT (swizzled into KPs) and Vs (natural)
#pragma unroll
        for (int l = 0; l < 4; l++) {
            int e = tid + l * 256;
            int r = e >> 4;           // key row 0..63
            int h4 = e & 15;
            size_t gidx = ((size_t)b * Tn + s0 + r) * Hn + h4 * 4;
            float4 kv = *(const float4*)&g_k[gidx];
            int pc = r ^ ((h4 & 7) << 2);
            KPs[(h4 * 4 + 0) * 64 + pc] = kv.x;
            KPs[(h4 * 4 + 1) * 64 + pc] = kv.y;
            KPs[(h4 * 4 + 2) * 64 + pc] = kv.z;
            KPs[(h4 * 4 + 3) * 64 + pc] = kv.w;
            *(float4*)&Vs[r * 64 + h4 * 4] = *(const float4*)&g_v[gidx];
        }
        __syncthreads();

        // S = Q K^T  (64 h-steps, f32x2 packed)
        unsigned long long s2[4][2];
#pragma unroll
        for (int i = 0; i < 4; i++) { s2[i][0] = 0ull; s2[i][1] = 0ull; }
#pragma unroll
        for (int h = 0; h < 64; h++) {
            const int xh = ((h >> 2) & 7) << 2;
            float4 a = *(const float4*)&QsT[h * 64 + ((ty * 4) ^ xh)];
            ulonglong2 bb = *(const ulonglong2*)&KPs[h * 64 + ((tx * 4) ^ xh)];
            unsigned long long a0 = pk2(a.x, a.x);
            unsigned long long a1 = pk2(a.y, a.y);
            unsigned long long a2v = pk2(a.z, a.z);
            unsigned long long a3 = pk2(a.w, a.w);
            FMA2(s2[0][0], a0, bb.x); FMA2(s2[0][1], a0, bb.y);
            FMA2(s2[1][0], a1, bb.x); FMA2(s2[1][1], a1, bb.y);
            FMA2(s2[2][0], a2v, bb.x); FMA2(s2[2][1], a2v, bb.y);
            FMA2(s2[3][0], a3, bb.x); FMA2(s2[3][1], a3, bb.y);
        }

        float s[4][4];
#pragma unroll
        for (int i = 0; i < 4; i++) {
            upk2(s2[i][0], s[i][0], s[i][1]);
            upk2(s2[i][1], s[i][2], s[i][3]);
        }
        // Causal mask (only needed on the diagonal tile)
        if (st == qt) {
#pragma unroll
            for (int i = 0; i < 4; i++)
#pragma unroll
                for (int j = 0; j < 4; j++)
                    if (tx * 4 + j > ty * 4 + i) s[i][j] = -1e30f;
        }

        // Online softmax update
        float mt[4], f[4], rs[4];
#pragma unroll
        for (int i = 0; i < 4; i++) {
            mt[i] = fmaxf(fmaxf(s[i][0], s[i][1]), fmaxf(s[i][2], s[i][3]));
#pragma unroll
            for (int off = 8; off >= 1; off >>= 1)
                mt[i] = fmaxf(mt[i], __shfl_xor_sync(0xffffffffu, mt[i], off));
            float mn = fmaxf(m_i[i], mt[i]);
            f[i] = __expf(m_i[i] - mn);
            m_i[i] = mn;
            float r = 0.f;
#pragma unroll
            for (int j = 0; j < 4; j++) {
                s[i][j] = __expf(s[i][j] - mn);
                r += s[i][j];
            }
#pragma unroll
            for (int off = 8; off >= 1; off >>= 1)
                r += __shfl_xor_sync(0xffffffffu, r, off);
            rs[i] = r;
            l_i[i] = l_i[i] * f[i] + rs[i];
            unsigned long long f2 = pk2(f[i], f[i]);
            MUL2(o2[i][0], o2[i][0], f2);
            MUL2(o2[i][1], o2[i][1], f2);
        }

        __syncthreads();  // all warps done reading K^T from KPs
        // Write P^T (swizzled) into KPs: PsT[s][r], s = tx*4+j, r = ty*4+i
#pragma unroll
        for (int j = 0; j < 4; j++)
#pragma unroll
            for (int i = 0; i < 4; i++)
                KPs[(tx * 4 + j) * 64 + ((ty * 4 + i) ^ ((tx & 7) << 2))] = s[i][j];
        __syncthreads();

        // O += P V  (64 s-steps, f32x2 packed)
#pragma unroll
        for (int sI = 0; sI < 64; sI++) {
            const int xs = ((sI >> 2) & 7) << 2;
            float4 a = *(const float4*)&KPs[sI * 64 + ((ty * 4) ^ xs)];
            ulonglong2 bb = *(const ulonglong2*)&Vs[sI * 64 + tx * 4];
            unsigned long long a0 = pk2(a.x, a.x);
            unsigned long long a1 = pk2(a.y, a.y);
            unsigned long long a2v = pk2(a.z, a.z);
            unsigned long long a3 = pk2(a.w, a.w);
            FMA2(o2[0][0], a0, bb.x); FMA2(o2[0][1], a0, bb.y);
            FMA2(o2[1][0], a1, bb.x); FMA2(o2[1][1], a1, bb.y);
            FMA2(o2[2][0], a2v, bb.x); FMA2(o2[2][1], a2v, bb.y);
            FMA2(o2[3][0], a3, bb.x); FMA2(o2[3][1], a3, bb.y);
        }
    }

    // Epilogue: normalize and store
#pragma unroll
    for (int i = 0; i < 4; i++) {
        float inv = 1.0f / l_i[i];
        float4 v;
        upk2(o2[i][0], v.x, v.y);
        upk2(o2[i][1], v.z, v.w);
        v.x *= inv; v.y *= inv; v.z *= inv; v.w *= inv;
        *(float4*)&out[((size_t)b * Tn + q0 + ty * 4 + i) * Hn + tx * 4] = v;
    }
}

// ================= launch =================
extern "C" void kernel_launch(void* const* d_in, const int* in_sizes, int n_in,
                              void* d_out, int out_size)
{
    const float* x  = (const float*)d_in[0];
    const float* wq = (const float*)d_in[1];
    const float* wk = (const float*)d_in[2];
    const float* wv = (const float*)d_in[3];
    float* out = (float*)d_out;

    dim3 g1((Bn * Tn) / 64, 3);
    qkv_kernel<<<g1, 256>>>(x, wq, wk, wv);

    dim3 g2(Tn / 64, Bn);
    attn_kernel<<<g2, 256>>>(out);
}

// round 3
// speedup vs baseline: 1.3245x; 1.3245x over previous
#include <cuda_runtime.h>
#include <cstdint>

#define Bn 16
#define Tn 2048
#define Cn 1024
#define Hn 64

// Scratch for Q, K, V projections (8 MB each).
__device__ float g_q[Bn * Tn * Hn];
__device__ float g_k[Bn * Tn * Hn];
__device__ float g_v[Bn * Tn * Hn];

// ---------------- helpers ----------------
// tf32 split: x ~= hi + lo, both tf32-representable (stored as fp32 bit patterns)
__device__ __forceinline__ void sp(float x, uint32_t& h, uint32_t& l) {
    asm("cvt.rna.tf32.f32 %0, %1;" : "=r"(h) : "f"(x));
    float r = x - __uint_as_float(h);
    asm("cvt.rna.tf32.f32 %0, %1;" : "=r"(l) : "f"(r));
}
__device__ __forceinline__ uint32_t tf32r(float x) {
    uint32_t h;
    asm("cvt.rna.tf32.f32 %0, %1;" : "=r"(h) : "f"(x));
    return h;
}

// m16n8k8 tf32 mma, D = A*B + D (fp32 accum)
__device__ __forceinline__ void mma8(float c[4],
                                     uint32_t a0, uint32_t a1, uint32_t a2, uint32_t a3,
                                     uint32_t b0, uint32_t b1) {
    asm volatile(
        "mma.sync.aligned.m16n8k8.row.col.f32.tf32.tf32.f32 "
        "{%0,%1,%2,%3}, {%4,%5,%6,%7}, {%8,%9}, {%0,%1,%2,%3};"
        : "+f"(c[0]), "+f"(c[1]), "+f"(c[2]), "+f"(c[3])
        : "r"(a0), "r"(a1), "r"(a2), "r"(a3), "r"(b0), "r"(b1));
}

// k-slot interleave within 8-groups so (k, k+4) pairs are adjacent -> LDS.64 frags
__device__ __forceinline__ int kslot(int i) {
    return (i & ~7) + ((i & 3) << 1) + ((i >> 2) & 1);
}

// ================= Kernel 1: QKV projection (mma.sync tf32 3x) =================
// grid = (256, 3), block = 128 (4 warps, each m32 x n64). M_TILE=128, K chunks of 32.
__global__ __launch_bounds__(128, 4) void qkv_kernel(
    const float* __restrict__ x,
    const float* __restrict__ wq,
    const float* __restrict__ wk,
    const float* __restrict__ wv)
{
    __shared__ __align__(16) float As[128 * 36];  // [m][k], raw fp32
    __shared__ __align__(16) float Bs[64 * 40];   // [n][k-interleaved], raw fp32

    const int which = blockIdx.y;
    const float* w = (which == 0) ? wq : (which == 1) ? wk : wv;
    float* out = (which == 0) ? g_q : (which == 1) ? g_k : g_v;

    const int m0 = blockIdx.x * 128;
    const int tid = threadIdx.x;
    const int wid = tid >> 5;
    const int lane = tid & 31;
    const int lr = lane >> 2;   // 0..7
    const int lc = lane & 3;    // 0..3

    float acc[2][8][4];
#pragma unroll
    for (int mt = 0; mt < 2; mt++)
#pragma unroll
        for (int nt = 0; nt < 8; nt++)
#pragma unroll
            for (int i = 0; i < 4; i++) acc[mt][nt][i] = 0.f;

    for (int kt = 0; kt < Cn / 32; kt++) {
        // fill As [128][32] (pad 36)
#pragma unroll
        for (int l = 0; l < 8; l++) {
            int idx = tid + l * 128;          // 0..1023 float4 slots
            int row = idx >> 3;
            int c4 = (idx & 7) * 4;
            *(float4*)&As[row * 36 + c4] =
                *(const float4*)&x[(size_t)(m0 + row) * Cn + kt * 32 + c4];
        }
        // fill Bs [64 n][32 k interleaved] from W[k][n]
#pragma unroll
        for (int l = 0; l < 4; l++) {
            int idx = tid + l * 128;          // 0..511
            int k = idx >> 4;                 // 0..31
            int n4 = (idx & 15) * 4;
            float4 v = *(const float4*)&w[(size_t)(kt * 32 + k) * Hn + n4];
            int ks = kslot(k);
            Bs[(n4 + 0) * 40 + ks] = v.x;
            Bs[(n4 + 1) * 40 + ks] = v.y;
            Bs[(n4 + 2) * 40 + ks] = v.z;
            Bs[(n4 + 3) * 40 + ks] = v.w;
        }
        __syncthreads();

#pragma unroll
        for (int ks = 0; ks < 4; ks++) {
            uint32_t ah[2][4], al[2][4];
#pragma unroll
            for (int mt = 0; mt < 2; mt++) {
                int r = wid * 32 + mt * 16 + lr;
                int c = ks * 8 + lc;
                sp(As[r * 36 + c],            ah[mt][0], al[mt][0]);
                sp(As[(r + 8) * 36 + c],      ah[mt][1], al[mt][1]);
                sp(As[r * 36 + c + 4],        ah[mt][2], al[mt][2]);
                sp(As[(r + 8) * 36 + c + 4],  ah[mt][3], al[mt][3]);
            }
#pragma unroll
            for (int nt = 0; nt < 8; nt++) {
                float2 br = *(const float2*)&Bs[(nt * 8 + lr) * 40 + ks * 8 + 2 * lc];
                uint32_t bh0, bl0, bh1, bl1;
                sp(br.x, bh0, bl0);
                sp(br.y, bh1, bl1);
#pragma unroll
                for (int mt = 0; mt < 2; mt++) {
                    mma8(acc[mt][nt], ah[mt][0], ah[mt][1], ah[mt][2], ah[mt][3], bh0, bh1);
                    mma8(acc[mt][nt], ah[mt][0], ah[mt][1], ah[mt][2], ah[mt][3], bl0, bl1);
                    mma8(acc[mt][nt], al[mt][0], al[mt][1], al[mt][2], al[mt][3], bh0, bh1);
                }
            }
        }
        __syncthreads();
    }

    // epilogue
#pragma unroll
    for (int mt = 0; mt < 2; mt++) {
        int r0 = m0 + wid * 32 + mt * 16 + lr;
        int r1 = r0 + 8;
#pragma unroll
        for (int nt = 0; nt < 8; nt++) {
            int col = nt * 8 + 2 * lc;
            *(float2*)&out[(size_t)r0 * Hn + col] = make_float2(acc[mt][nt][0], acc[mt][nt][1]);
            *(float2*)&out[(size_t)r1 * Hn + col] = make_float2(acc[mt][nt][2], acc[mt][nt][3]);
        }
    }
}

// ================= Kernel 2: flash attention (mma.sync tf32 3x) =================
// grid = (16, 16), block = 256 (8 warps, each m16 x n64). Q_TILE=128, KV_TILE=64.
// Dynamic SMEM: Kh[64*72] | Kl[64*72] | VhT[64*72] | VlT[64*72]; P overlays Kh+Kl.
__global__ __launch_bounds__(256, 2) void attn_kernel(float* __restrict__ out)
{
    extern __shared__ float dsm[];
    float* Kh  = dsm;                 // [s][kslot(h)]
    float* Kl  = dsm + 64 * 72;
    float* Ps  = dsm;                 // [128][kslot(s)] overlays Kh+Kl
    float* VhT = dsm + 2 * 64 * 72;   // [h][kslot(s)]
    float* VlT = dsm + 3 * 64 * 72;

    const int b = blockIdx.y;
    const int qt = 15 - blockIdx.x;   // heavy first
    const int q0 = qt * 128;
    const size_t bT = (size_t)b * Tn;
    const int tid = threadIdx.x;
    const int wid = tid >> 5;
    const int lane = tid & 31;
    const int lr = lane >> 2;
    const int lc = lane & 3;

    const int r0l = wid * 16 + lr;    // local query rows for c0/c1
    const int r1l = r0l + 8;          // for c2/c3

    // Q fragments in registers, pre-scaled by H^-0.5 = 0.125
    float qa[8][4];
#pragma unroll
    for (int ks = 0; ks < 8; ks++) {
        qa[ks][0] = g_q[(bT + q0 + r0l) * Hn + ks * 8 + lc] * 0.125f;
        qa[ks][1] = g_q[(bT + q0 + r1l) * Hn + ks * 8 + lc] * 0.125f;
        qa[ks][2] = g_q[(bT + q0 + r0l) * Hn + ks * 8 + lc + 4] * 0.125f;
        qa[ks][3] = g_q[(bT + q0 + r1l) * Hn + ks * 8 + lc + 4] * 0.125f;
    }

    float o[8][4];
    float mrow[2] = { -1e30f, -1e30f };
    float lrow[2] = { 0.f, 0.f };
#pragma unroll
    for (int nt = 0; nt < 8; nt++)
#pragma unroll
        for (int i = 0; i < 4; i++) o[nt][i] = 0.f;

    const int n_iter = 2 * qt + 2;
    for (int st = 0; st < n_iter; st++) {
        const int s0 = st * 64;
        __syncthreads();  // previous iteration's PV reads complete

        // fill K (hi/lo, k-dim = h interleaved) and V^T (hi/lo, k-dim = s interleaved)
#pragma unroll
        for (int l = 0; l < 4; l++) {
            int e = tid + l * 256;
            int s = e >> 4;
            int h4 = (e & 15) * 4;
            size_t gidx = (bT + s0 + s) * Hn + h4;
            float4 kv = *(const float4*)&g_k[gidx];
            float4 vv = *(const float4*)&g_v[gidx];
            float kk[4] = { kv.x, kv.y, kv.z, kv.w };
            float vvv[4] = { vv.x, vv.y, vv.z, vv.w };
            int sslot = kslot(s);
#pragma unroll
            for (int j = 0; j < 3 + 1; j++) {
                uint32_t h, lo;
                sp(kk[j], h, lo);
                int hs = kslot(h4 + j);
                Kh[s * 72 + hs] = __uint_as_float(h);
                Kl[s * 72 + hs] = __uint_as_float(lo);
                sp(vvv[j], h, lo);
                VhT[(h4 + j) * 72 + sslot] = __uint_as_float(h);
                VlT[(h4 + j) * 72 + sslot] = __uint_as_float(lo);
            }
        }
        __syncthreads();

        // ---- S = Q K^T ----
        float sacc[8][4];
#pragma unroll
        for (int nt = 0; nt < 8; nt++)
#pragma unroll
            for (int i = 0; i < 4; i++) sacc[nt][i] = 0.f;

#pragma unroll
        for (int ks = 0; ks < 8; ks++) {
            uint32_t ah[4], al[4];
            sp(qa[ks][0], ah[0], al[0]);
            sp(qa[ks][1], ah[1], al[1]);
            sp(qa[ks][2], ah[2], al[2]);
            sp(qa[ks][3], ah[3], al[3]);
#pragma unroll
            for (int nt = 0; nt < 8; nt++) {
                int boff = (nt * 8 + lr) * 72 + ks * 8 + 2 * lc;
                float2 bh = *(const float2*)&Kh[boff];
                float2 bl = *(const float2*)&Kl[boff];
                uint32_t bh0 = __float_as_uint(bh.x), bh1 = __float_as_uint(bh.y);
                uint32_t bl0 = __float_as_uint(bl.x), bl1 = __float_as_uint(bl.y);
                mma8(sacc[nt], ah[0], ah[1], ah[2], ah[3], bh0, bh1);
                mma8(sacc[nt], ah[0], ah[1], ah[2], ah[3], bl0, bl1);
                mma8(sacc[nt], al[0], al[1], al[2], al[3], bh0, bh1);
            }
        }

        // ---- causal mask (only tiles overlapping/above diagonal) ----
        if (st >= 2 * qt) {
            int r0g = q0 + r0l, r1g = q0 + r1l;
#pragma unroll
            for (int nt = 0; nt < 8; nt++) {
                int cg = s0 + nt * 8 + 2 * lc;
                if (cg > r0g)     sacc[nt][0] = -1e30f;
                if (cg + 1 > r0g) sacc[nt][1] = -1e30f;
                if (cg > r1g)     sacc[nt][2] = -1e30f;
                if (cg + 1 > r1g) sacc[nt][3] = -1e30f;
            }
        }

        // ---- online softmax ----
        float mx0 = -1e30f, mx1 = -1e30f;
#pragma unroll
        for (int nt = 0; nt < 8; nt++) {
            mx0 = fmaxf(mx0, fmaxf(sacc[nt][0], sacc[nt][1]));
            mx1 = fmaxf(mx1, fmaxf(sacc[nt][2], sacc[nt][3]));
        }
        mx0 = fmaxf(mx0, __shfl_xor_sync(0xffffffffu, mx0, 1));
        mx0 = fmaxf(mx0, __shfl_xor_sync(0xffffffffu, mx0, 2));
        mx1 = fmaxf(mx1, __shfl_xor_sync(0xffffffffu, mx1, 1));
        mx1 = fmaxf(mx1, __shfl_xor_sync(0xffffffffu, mx1, 2));

        float mn0 = fmaxf(mrow[0], mx0);
        float mn1 = fmaxf(mrow[1], mx1);
        float f0 = __expf(mrow[0] - mn0);
        float f1 = __expf(mrow[1] - mn1);
        mrow[0] = mn0; mrow[1] = mn1;

        float sum0 = 0.f, sum1 = 0.f;
#pragma unroll
        for (int nt = 0; nt < 8; nt++) {
            sacc[nt][0] = __expf(sacc[nt][0] - mn0);
            sacc[nt][1] = __expf(sacc[nt][1] - mn0);
            sacc[nt][2] = __expf(sacc[nt][2] - mn1);
            sacc[nt][3] = __expf(sacc[nt][3] - mn1);
            sum0 += sacc[nt][0] + sacc[nt][1];
            sum1 += sacc[nt][2] + sacc[nt][3];
        }
        sum0 += __shfl_xor_sync(0xffffffffu, sum0, 1);
        sum0 += __shfl_xor_sync(0xffffffffu, sum0, 2);
        sum1 += __shfl_xor_sync(0xffffffffu, sum1, 1);
        sum1 += __shfl_xor_sync(0xffffffffu, sum1, 2);
        lrow[0] = lrow[0] * f0 + sum0;
        lrow[1] = lrow[1] * f1 + sum1;

#pragma unroll
        for (int nt = 0; nt < 8; nt++) {
            o[nt][0] *= f0; o[nt][1] *= f0;
            o[nt][2] *= f1; o[nt][3] *= f1;
        }

        __syncthreads();  // all warps done reading K tiles before P overlay

        // ---- write P (raw fp32, k-dim = s interleaved); rows are warp-local ----
#pragma unroll
        for (int nt = 0; nt < 8; nt++) {
            int n0 = nt * 8 + 2 * lc;
            int sl0 = kslot(n0), sl1 = kslot(n0 + 1);
            Ps[r0l * 72 + sl0] = sacc[nt][0];
            Ps[r0l * 72 + sl1] = sacc[nt][1];
            Ps[r1l * 72 + sl0] = sacc[nt][2];
            Ps[r1l * 72 + sl1] = sacc[nt][3];
        }
        __syncwarp();

        // ---- O += P V ----
#pragma unroll
        for (int ks = 0; ks < 8; ks++) {
            float2 p02 = *(const float2*)&Ps[r0l * 72 + ks * 8 + 2 * lc];
            float2 p13 = *(const float2*)&Ps[r1l * 72 + ks * 8 + 2 * lc];
            uint32_t ah[4], al[4];
            sp(p02.x, ah[0], al[0]);
            sp(p13.x, ah[1], al[1]);
            sp(p02.y, ah[2], al[2]);
            sp(p13.y, ah[3], al[3]);
#pragma unroll
            for (int nt = 0; nt < 8; nt++) {
                int boff = (nt * 8 + lr) * 72 + ks * 8 + 2 * lc;
                float2 bh = *(const float2*)&VhT[boff];
                float2 bl = *(const float2*)&VlT[boff];
                uint32_t bh0 = __float_as_uint(bh.x), bh1 = __float_as_uint(bh.y);
                uint32_t bl0 = __float_as_uint(bl.x), bl1 = __float_as_uint(bl.y);
                mma8(o[nt], ah[0], ah[1], ah[2], ah[3], bh0, bh1);
                mma8(o[nt], ah[0], ah[1], ah[2], ah[3], bl0, bl1);
                mma8(o[nt], al[0], al[1], al[2], al[3], bh0, bh1);
            }
        }
    }

    // ---- epilogue ----
    float inv0 = 1.0f / lrow[0];
    float inv1 = 1.0f / lrow[1];
#pragma unroll
    for (int nt = 0; nt < 8; nt++) {
        int col = nt * 8 + 2 * lc;
        *(float2*)&out[(bT + q0 + r0l) * Hn + col] =
            make_float2(o[nt][0] * inv0, o[nt][1] * inv0);
        *(float2*)&out[(bT + q0 + r1l) * Hn + col] =
            make_float2(o[nt][2] * inv1, o[nt][3] * inv1);
    }
}

// ================= launch =================
extern "C" void kernel_launch(void* const* d_in, const int* in_sizes, int n_in,
                              void* d_out, int out_size)
{
    const float* x  = (const float*)d_in[0];
    const float* wq = (const float*)d_in[1];
    const float* wk = (const float*)d_in[2];
    const float* wv = (const float*)d_in[3];
    float* out = (float*)d_out;

    dim3 g1((Bn * Tn) / 128, 3);
    qkv_kernel<<<g1, 128>>>(x, wq, wk, wv);

    const int attn_smem = 4 * 64 * 72 * 4;  // 73728 bytes
    cudaFuncSetAttribute(attn_kernel, cudaFuncAttributeMaxDynamicSharedMemorySize, attn_smem);
    dim3 g2(Tn / 128, Bn);
    attn_kernel<<<g2, 256, attn_smem>>>(out);
}

// round 6
// speedup vs baseline: 1.7929x; 1.3536x over previous
#include <cuda_runtime.h>
#include <cstdint>

#define Bn 16
#define Tn 2048
#define Cn 1024
#define Hn 64

// Precomputed global scratch
__device__ float g_q[Bn * Tn * Hn];        // pre-scaled by 0.125, [t][h]
__device__ float g_khi[Bn * Tn * Hn];      // [t][kslot(h)]
__device__ float g_klo[Bn * Tn * Hn];
__device__ float g_vhiT[Bn * Hn * Tn];     // [b][h][perm(t)]
__device__ float g_vloT[Bn * Hn * Tn];
__device__ float g_whi[3 * Cn * Hn];       // [which][kt][n][kslot(k)] tiles
__device__ float g_wlo[3 * Cn * Hn];

// ---------------- helpers ----------------
__device__ __forceinline__ void sp(float x, uint32_t& h, uint32_t& l) {
    asm("cvt.rna.tf32.f32 %0, %1;" : "=r"(h) : "f"(x));
    float r = x - __uint_as_float(h);
    asm("cvt.rna.tf32.f32 %0, %1;" : "=r"(l) : "f"(r));
}
__device__ __forceinline__ void mma8(float c[4],
                                     uint32_t a0, uint32_t a1, uint32_t a2, uint32_t a3,
                                     uint32_t b0, uint32_t b1) {
    asm volatile(
        "mma.sync.aligned.m16n8k8.row.col.f32.tf32.tf32.f32 "
        "{%0,%1,%2,%3}, {%4,%5,%6,%7}, {%8,%9}, {%0,%1,%2,%3};"
        : "+f"(c[0]), "+f"(c[1]), "+f"(c[2]), "+f"(c[3])
        : "r"(a0), "r"(a1), "r"(a2), "r"(a3), "r"(b0), "r"(b1));
}
// interleave within 8-groups: (k, k+4) adjacent -> LDS.64 B-fragments
__device__ __forceinline__ int kslot(int i) {
    return (i & ~7) + ((i & 3) << 1) + ((i >> 2) & 1);
}
__device__ __forceinline__ uint32_t smem_u32(const void* p) {
    uint32_t a;
    asm("{ .reg .u64 t; cvta.to.shared.u64 t, %1; cvt.u32.u64 %0, t; }" : "=r"(a) : "l"(p));
    return a;
}
#define CP16(dst, src) \
    asm volatile("cp.async.cg.shared.global [%0], [%1], 16;" :: "r"(dst), "l"(src))
#define CP_COMMIT() asm volatile("cp.async.commit_group;" ::: "memory")
#define CP_WAIT0()  asm volatile("cp.async.wait_group 0;" ::: "memory")

// ================= Kernel 0: W split (tiny) =================
// grid (32, 3), block 256. dst layout: ((which*32+kt)*64 + n)*32 + kslot(k)
__global__ void wsplit_kernel(const float* __restrict__ wq,
                              const float* __restrict__ wk,
                              const float* __restrict__ wv) {
    const int which = blockIdx.y, kt = blockIdx.x;
    const float* w = (which == 0) ? wq : (which == 1) ? wk : wv;
    const int tid = threadIdx.x;
#pragma unroll
    for (int i = 0; i < 8; i++) {
        int e = tid + i * 256;        // 0..2047
        int k = e >> 6, n = e & 63;
        uint32_t h, l;
        sp(w[(size_t)(kt * 32 + k) * Hn + n], h, l);
        int dst = ((which * 32 + kt) * 64 + n) * 32 + kslot(k);
        g_whi[dst] = __uint_as_float(h);
        g_wlo[dst] = __uint_as_float(l);
    }
}

// ================= Kernel 1: QKV projection =================
// grid (256, 3), block 128 (4 warps, m32 x n64). M_TILE=128, K chunks of 32.
__global__ __launch_bounds__(128, 4) void qkv_kernel(const float* __restrict__ x)
{
    __shared__ __align__(16) float As[128 * 36];
    __shared__ __align__(16) float Bh[64 * 40];
    __shared__ __align__(16) float Bl[64 * 40];

    const int which = blockIdx.y;
    const int m0 = blockIdx.x * 128;
    const int tid = threadIdx.x;
    const int wid = tid >> 5, lane = tid & 31;
    const int lr = lane >> 2, lc = lane & 3;

    const uint32_t AsA = smem_u32(As), BhA = smem_u32(Bh), BlA = smem_u32(Bl);

    float acc[2][8][4];
#pragma unroll
    for (int mt = 0; mt < 2; mt++)
#pragma unroll
        for (int nt = 0; nt < 8; nt++)
#pragma unroll
            for (int i = 0; i < 4; i++) acc[mt][nt][i] = 0.f;

    for (int kt = 0; kt < Cn / 32; kt++) {
        // A fill: 128 rows x 8 chunks of 16B = 1024 chunks
#pragma unroll
        for (int l = 0; l < 8; l++) {
            int idx = tid + l * 128;
            int row = idx >> 3, ch = idx & 7;
            CP16(AsA + (row * 36 + ch * 4) * 4,
                 x + (size_t)(m0 + row) * Cn + kt * 32 + ch * 4);
        }
        // B fill: hi/lo tiles, 64 rows x 8 chunks = 512 chunks each
        const size_t tb = (size_t)(which * 32 + kt) * 2048;
#pragma unroll
        for (int l = 0; l < 4; l++) {
            int idx = tid + l * 128;
            int n = idx >> 3, ch = idx & 7;
            CP16(BhA + (n * 40 + ch * 4) * 4, g_whi + tb + n * 32 + ch * 4);
            CP16(BlA + (n * 40 + ch * 4) * 4, g_wlo + tb + n * 32 + ch * 4);
        }
        CP_COMMIT();
        CP_WAIT0();
        __syncthreads();

#pragma unroll
        for (int ks = 0; ks < 4; ks++) {
            uint32_t ah[2][4], al[2][4];
#pragma unroll
            for (int mt = 0; mt < 2; mt++) {
                int r = wid * 32 + mt * 16 + lr;
                int c = ks * 8 + lc;
                sp(As[r * 36 + c],           ah[mt][0], al[mt][0]);
                sp(As[(r + 8) * 36 + c],     ah[mt][1], al[mt][1]);
                sp(As[r * 36 + c + 4],       ah[mt][2], al[mt][2]);
                sp(As[(r + 8) * 36 + c + 4], ah[mt][3], al[mt][3]);
            }
#pragma unroll
            for (int nt = 0; nt < 8; nt++) {
                int boff = (nt * 8 + lr) * 40 + ks * 8 + 2 * lc;
                float2 bhv = *(const float2*)&Bh[boff];
                float2 blv = *(const float2*)&Bl[boff];
                uint32_t bh0 = __float_as_uint(bhv.x), bh1 = __float_as_uint(bhv.y);
                uint32_t bl0 = __float_as_uint(blv.x), bl1 = __float_as_uint(blv.y);
#pragma unroll
                for (int mt = 0; mt < 2; mt++) {
                    mma8(acc[mt][nt], ah[mt][0], ah[mt][1], ah[mt][2], ah[mt][3], bh0, bh1);
                    mma8(acc[mt][nt], ah[mt][0], ah[mt][1], ah[mt][2], ah[mt][3], bl0, bl1);
                    mma8(acc[mt][nt], al[mt][0], al[mt][1], al[mt][2], al[mt][3], bh0, bh1);
                }
            }
        }
        __syncthreads();
    }

    // Epilogue by output kind
#pragma unroll
    for (int mt = 0; mt < 2; mt++) {
        int r0 = m0 + wid * 32 + mt * 16 + lr;
#pragma unroll
        for (int rr = 0; rr < 2; rr++) {
            int row = r0 + rr * 8;
#pragma unroll
            for (int nt = 0; nt < 8; nt++) {
                float v0 = acc[mt][nt][rr * 2 + 0];
                float v1 = acc[mt][nt][rr * 2 + 1];
                int col0 = nt * 8 + 2 * lc, col1 = col0 + 1;
                if (which == 0) {
                    *(float2*)&g_q[(size_t)row * Hn + col0] =
                        make_float2(v0 * 0.125f, v1 * 0.125f);
                } else if (which == 1) {
                    uint32_t h, l;
                    sp(v0, h, l);
                    g_khi[(size_t)row * Hn + kslot(col0)] = __uint_as_float(h);
                    g_klo[(size_t)row * Hn + kslot(col0)] = __uint_as_float(l);
                    sp(v1, h, l);
                    g_khi[(size_t)row * Hn + kslot(col1)] = __uint_as_float(h);
                    g_klo[(size_t)row * Hn + kslot(col1)] = __uint_as_float(l);
                } else {
                    int b = row >> 11, t = row & 2047;
                    int pt = kslot(t);
                    uint32_t h, l;
                    sp(v0, h, l);
                    g_vhiT[((size_t)(b * Hn + col0)) * Tn + pt] = __uint_as_float(h);
                    g_vloT[((size_t)(b * Hn + col0)) * Tn + pt] = __uint_as_float(l);
                    sp(v1, h, l);
                    g_vhiT[((size_t)(b * Hn + col1)) * Tn + pt] = __uint_as_float(h);
                    g_vloT[((size_t)(b * Hn + col1)) * Tn + pt] = __uint_as_float(l);
                }
            }
        }
    }
}

// ================= Kernel 2: flash attention =================
// grid 512 (heavy-first), block 128 (4 warps, each m16 x n64).
// Q_TILE=64, KV_TILE=64. Dynamic SMEM 73728B -> 3 CTAs/SM.
__global__ __launch_bounds__(128, 3) void attn_kernel(float* __restrict__ out)
{
    extern __shared__ float dsm[];
    float* Kh  = dsm;                 // [s][kslot(h)] pad 72
    float* Kl  = dsm + 64 * 72;
    float* VhT = dsm + 2 * 64 * 72;   // [h][kslot(s)] pad 72
    float* VlT = dsm + 3 * 64 * 72;
    float* Ps  = Kh;                  // P overlay [q][kslot(s)]

    const int qt = 31 - (blockIdx.x >> 4);
    const int b  = blockIdx.x & 15;
    const int q0 = qt * 64;
    const size_t bT = (size_t)b * Tn;
    const int tid = threadIdx.x;
    const int wid = tid >> 5, lane = tid & 31;
    const int lr = lane >> 2, lc = lane & 3;
    const int r0l = wid * 16 + lr, r1l = r0l + 8;

    const uint32_t KhA = smem_u32(Kh), KlA = smem_u32(Kl);
    const uint32_t VhA = smem_u32(VhT), VlA = smem_u32(VlT);

    // Q fragments (already scaled in qkv epilogue)
    float qa[8][4];
#pragma unroll
    for (int ks = 0; ks < 8; ks++) {
        qa[ks][0] = g_q[(bT + q0 + r0l) * Hn + ks * 8 + lc];
        qa[ks][1] = g_q[(bT + q0 + r1l) * Hn + ks * 8 + lc];
        qa[ks][2] = g_q[(bT + q0 + r0l) * Hn + ks * 8 + lc + 4];
        qa[ks][3] = g_q[(bT + q0 + r1l) * Hn + ks * 8 + lc + 4];
    }

    float o[8][4];
    float mrow[2] = { -1e30f, -1e30f };
    float lrow[2] = { 0.f, 0.f };
#pragma unroll
    for (int nt = 0; nt < 8; nt++)
#pragma unroll
        for (int i = 0; i < 4; i++) o[nt][i] = 0.f;

    for (int st = 0; st <= qt; st++) {
        const int s0 = st * 64;
        __syncthreads();  // previous iteration fully consumed

        // cp.async fill: warp w owns array w.
        // Each array: 64 rows x 16 chunks of 16B = 1024 chunks -> 32 per lane.
#pragma unroll
        for (int i = 0; i < 32; i++) {
            int c = lane + i * 32;        // 0..1023
            int row = c >> 4, ch = c & 15;
            if (wid == 0)
                CP16(KhA + row * 288 + ch * 16, g_khi + ((bT + s0 + row) << 6) + ch * 4);
            else if (wid == 1)
                CP16(KlA + row * 288 + ch * 16, g_klo + ((bT + s0 + row) << 6) + ch * 4);
            else if (wid == 2)
                CP16(VhA + row * 288 + ch * 16,
                     g_vhiT + ((size_t)((b << 6) + row)) * Tn + s0 + ch * 4);
            else
                CP16(VlA + row * 288 + ch * 16,
                     g_vloT + ((size_t)((b << 6) + row)) * Tn + s0 + ch * 4);
        }
        CP_COMMIT();
        CP_WAIT0();
        __syncthreads();

        // ---- S = Q K^T ----
        float sacc[8][4];
#pragma unroll
        for (int nt = 0; nt < 8; nt++)
#pragma unroll
            for (int i = 0; i < 4; i++) sacc[nt][i] = 0.f;

#pragma unroll
        for (int ks = 0; ks < 8; ks++) {
            uint32_t ah[4], al[4];
            sp(qa[ks][0], ah[0], al[0]);
            sp(qa[ks][1], ah[1], al[1]);
            sp(qa[ks][2], ah[2], al[2]);
            sp(qa[ks][3], ah[3], al[3]);
#pragma unroll
            for (int nt = 0; nt < 8; nt++) {
                int boff = (nt * 8 + lr) * 72 + ks * 8 + 2 * lc;
                float2 bh = *(const float2*)&Kh[boff];
                float2 bl = *(const float2*)&Kl[boff];
                uint32_t bh0 = __float_as_uint(bh.x), bh1 = __float_as_uint(bh.y);
                uint32_t bl0 = __float_as_uint(bl.x), bl1 = __float_as_uint(bl.y);
                mma8(sacc[nt], ah[0], ah[1], ah[2], ah[3], bh0, bh1);
                mma8(sacc[nt], ah[0], ah[1], ah[2], ah[3], bl0, bl1);
                mma8(sacc[nt], al[0], al[1], al[2], al[3], bh0, bh1);
            }
        }

        if (st == qt) {  // diagonal tile
            int r0g = q0 + r0l, r1g = q0 + r1l;
#pragma unroll
            for (int nt = 0; nt < 8; nt++) {
                int cg = s0 + nt * 8 + 2 * lc;
                if (cg > r0g)     sacc[nt][0] = -1e30f;
                if (cg + 1 > r0g) sacc[nt][1] = -1e30f;
                if (cg > r1g)     sacc[nt][2] = -1e30f;
                if (cg + 1 > r1g) sacc[nt][3] = -1e30f;
            }
        }

        // ---- online softmax ----
        float mx0 = -1e30f, mx1 = -1e30f;
#pragma unroll
        for (int nt = 0; nt < 8; nt++) {
            mx0 = fmaxf(mx0, fmaxf(sacc[nt][0], sacc[nt][1]));
            mx1 = fmaxf(mx1, fmaxf(sacc[nt][2], sacc[nt][3]));
        }
        mx0 = fmaxf(mx0, __shfl_xor_sync(0xffffffffu, mx0, 1));
        mx0 = fmaxf(mx0, __shfl_xor_sync(0xffffffffu, mx0, 2));
        mx1 = fmaxf(mx1, __shfl_xor_sync(0xffffffffu, mx1, 1));
        mx1 = fmaxf(mx1, __shfl_xor_sync(0xffffffffu, mx1, 2));

        float mn0 = fmaxf(mrow[0], mx0), mn1 = fmaxf(mrow[1], mx1);
        float f0 = __expf(mrow[0] - mn0), f1 = __expf(mrow[1] - mn1);
        mrow[0] = mn0; mrow[1] = mn1;

        float sum0 = 0.f, sum1 = 0.f;
#pragma unroll
        for (int nt = 0; nt < 8; nt++) {
            sacc[nt][0] = __expf(sacc[nt][0] - mn0);
            sacc[nt][1] = __expf(sacc[nt][1] - mn0);
            sacc[nt][2] = __expf(sacc[nt][2] - mn1);
            sacc[nt][3] = __expf(sacc[nt][3] - mn1);
            sum0 += sacc[nt][0] + sacc[nt][1];
            sum1 += sacc[nt][2] + sacc[nt][3];
        }
        sum0 += __shfl_xor_sync(0xffffffffu, sum0, 1);
        sum0 += __shfl_xor_sync(0xffffffffu, sum0, 2);
        sum1 += __shfl_xor_sync(0xffffffffu, sum1, 1);
        sum1 += __shfl_xor_sync(0xffffffffu, sum1, 2);
        lrow[0] = lrow[0] * f0 + sum0;
        lrow[1] = lrow[1] * f1 + sum1;

#pragma unroll
        for (int nt = 0; nt < 8; nt++) {
            o[nt][0] *= f0; o[nt][1] *= f0;
            o[nt][2] *= f1; o[nt][3] *= f1;
        }

        __syncthreads();  // K reads done before P overlay

#pragma unroll
        for (int nt = 0; nt < 8; nt++) {
            int n0 = nt * 8 + 2 * lc;
            int sl0 = kslot(n0), sl1 = kslot(n0 + 1);
            Ps[r0l * 72 + sl0] = sacc[nt][0];
            Ps[r0l * 72 + sl1] = sacc[nt][1];
            Ps[r1l * 72 + sl0] = sacc[nt][2];
            Ps[r1l * 72 + sl1] = sacc[nt][3];
        }
        __syncwarp();  // PV reads only this warp's rows

        // ---- O += P V ----
#pragma unroll
        for (int ks = 0; ks < 8; ks++) {
            float2 p02 = *(const float2*)&Ps[r0l * 72 + ks * 8 + 2 * lc];
            float2 p13 = *(const float2*)&Ps[r1l * 72 + ks * 8 + 2 * lc];
            uint32_t ah[4], al[4];
            sp(p02.x, ah[0], al[0]);
            sp(p13.x, ah[1], al[1]);
            sp(p02.y, ah[2], al[2]);
            sp(p13.y, ah[3], al[3]);
#pragma unroll
            for (int nt = 0; nt < 8; nt++) {
                int boff = (nt * 8 + lr) * 72 + ks * 8 + 2 * lc;
                float2 bh = *(const float2*)&VhT[boff];
                float2 bl = *(const float2*)&VlT[boff];
                uint32_t bh0 = __float_as_uint(bh.x), bh1 = __float_as_uint(bh.y);
                uint32_t bl0 = __float_as_uint(bl.x), bl1 = __float_as_uint(bl.y);
                mma8(o[nt], ah[0], ah[1], ah[2], ah[3], bh0, bh1);
                mma8(o[nt], ah[0], ah[1], ah[2], ah[3], bl0, bl1);
                mma8(o[nt], al[0], al[1], al[2], al[3], bh0, bh1);
            }
        }
    }

    float inv0 = 1.0f / lrow[0], inv1 = 1.0f / lrow[1];
#pragma unroll
    for (int nt = 0; nt < 8; nt++) {
        int col = nt * 8 + 2 * lc;
        *(float2*)&out[(bT + q0 + r0l) * Hn + col] =
            make_float2(o[nt][0] * inv0, o[nt][1] * inv0);
        *(float2*)&out[(bT + q0 + r1l) * Hn + col] =
            make_float2(o[nt][2] * inv1, o[nt][3] * inv1);
    }
}

// ================= launch =================
extern "C" void kernel_launch(void* const* d_in, const int* in_sizes, int n_in,
                              void* d_out, int out_size)
{
    const float* x  = (const float*)d_in[0];
    const float* wq = (const float*)d_in[1];
    const float* wk = (const float*)d_in[2];
    const float* wv = (const float*)d_in[3];
    float* out = (float*)d_out;

    wsplit_kernel<<<dim3(32, 3), 256>>>(wq, wk, wv);
    qkv_kernel<<<dim3((Bn * Tn) / 128, 3), 128>>>(x);

    const int attn_smem = 4 * 64 * 72 * 4;  // 73728 B
    cudaFuncSetAttribute(attn_kernel, cudaFuncAttributeMaxDynamicSharedMemorySize, attn_smem);
    attn_kernel<<<512, 128, attn_smem>>>(out);
}

// round 8
// speedup vs baseline: 3.4980x; 1.9511x over previous
#include <cuda_runtime.h>
#include <cstdint>

#define Bn 16
#define Tn 2048
#define Cn 1024
#define Hn 64

// ---------------- global scratch (pre-split bf16 operands) ----------------
__device__ uint32_t g_qhi[Bn * Tn * 32];   // Q scaled, bf16-pair words [t][kslot(h/2)]
__device__ uint32_t g_qlo[Bn * Tn * 32];
__device__ uint32_t g_khi[Bn * Tn * 32];   // K words [t][kslot(h/2)]
__device__ uint32_t g_klo[Bn * Tn * 32];
__device__ unsigned short g_vhiT[Bn * Hn * Tn];  // V^T bf16 [b][h][eperm(t)]
__device__ unsigned short g_vloT[Bn * Hn * Tn];
__device__ uint32_t g_whi[3 * 32 * 64 * 16];     // W words [which][kt][n][kslot(k/2)]
__device__ uint32_t g_wlo[3 * 32 * 64 * 16];

// ---------------- helpers ----------------
__device__ __forceinline__ unsigned short b16(float x) {
    unsigned short h;
    asm("cvt.rn.bf16.f32 %0, %1;" : "=h"(h) : "f"(x));
    return h;
}
__device__ __forceinline__ float fb16(unsigned short h) {
    return __uint_as_float((uint32_t)h << 16);
}
__device__ __forceinline__ uint32_t pkb(unsigned short lo, unsigned short hi) {
    uint32_t r;
    asm("mov.b32 %0, {%1, %2};" : "=r"(r) : "h"(lo), "h"(hi));
    return r;
}
// split pair (x0 = k-even, x1 = k-odd) into hi-word and lo-word
__device__ __forceinline__ void spb2(float x0, float x1, uint32_t& hw, uint32_t& lw) {
    unsigned short h0 = b16(x0), h1 = b16(x1);
    unsigned short l0 = b16(x0 - fb16(h0)), l1 = b16(x1 - fb16(h1));
    hw = pkb(h0, h1);
    lw = pkb(l0, l1);
}
// bf16 m16n8k16 mma, fp32 accum
__device__ __forceinline__ void mmab(float c[4],
                                     uint32_t a0, uint32_t a1, uint32_t a2, uint32_t a3,
                                     uint32_t b0, uint32_t b1) {
    asm volatile(
        "mma.sync.aligned.m16n8k16.row.col.f32.bf16.bf16.f32 "
        "{%0,%1,%2,%3}, {%4,%5,%6,%7}, {%8,%9}, {%0,%1,%2,%3};"
        : "+f"(c[0]), "+f"(c[1]), "+f"(c[2]), "+f"(c[3])
        : "r"(a0), "r"(a1), "r"(a2), "r"(a3), "r"(b0), "r"(b1));
}
// word interleave within 8-groups: (w, w+4) adjacent
__device__ __forceinline__ int kslot(int w) {
    return (w & ~7) + 2 * (w & 3) + ((w >> 2) & 1);
}
// element permutation for V^T rows so contiguous copy yields kslot word order
__device__ __forceinline__ int eperm(int t) {
    int w = (t >> 1) & 7;
    int sl = 2 * (w & 3) + ((w >> 2) & 1);
    return (t & ~15) + sl * 2 + (t & 1);
}
__device__ __forceinline__ uint32_t smem_u32(const void* p) {
    uint32_t a;
    asm("{ .reg .u64 t; cvta.to.shared.u64 t, %1; cvt.u32.u64 %0, t; }" : "=r"(a) : "l"(p));
    return a;
}
#define CP16(dst, src) \
    asm volatile("cp.async.cg.shared.global [%0], [%1], 16;" :: "r"(dst), "l"(src))
#define CP_COMMIT() asm volatile("cp.async.commit_group;" ::: "memory")
#define CP_WAIT0()  asm volatile("cp.async.wait_group 0;" ::: "memory")

// ================= Kernel 0: W split -> bf16 words =================
// grid (32, 3), block 256. dst: ((which*32+kt)*64 + n)*16 + kslot(k/2)
__global__ void wsplit_kernel(const float* __restrict__ wq,
                              const float* __restrict__ wk,
                              const float* __restrict__ wv) {
    const int which = blockIdx.y, kt = blockIdx.x;
    const float* w = (which == 0) ? wq : (which == 1) ? wk : wv;
    const int tid = threadIdx.x;
#pragma unroll
    for (int i = 0; i < 4; i++) {
        int e = tid + i * 256;        // 0..1023 words
        int n = e & 63, wp = e >> 6;  // wp 0..15
        float x0 = w[(size_t)(kt * 32 + 2 * wp) * Hn + n];
        float x1 = w[(size_t)(kt * 32 + 2 * wp + 1) * Hn + n];
        uint32_t hw, lw;
        spb2(x0, x1, hw, lw);
        int dst = ((which * 32 + kt) * 64 + n) * 16 + kslot(wp);
        g_whi[dst] = hw;
        g_wlo[dst] = lw;
    }
}

// ================= Kernel 1: QKV projection (bf16 3-split) =================
// grid (256, 3), block 128 (4 warps, m32 x n64). M_TILE=128, K chunks of 32.
__global__ __launch_bounds__(128, 4) void qkv_kernel(const float* __restrict__ x)
{
    __shared__ __align__(16) float As[128 * 40];     // fp32 [m][k] pad 40
    __shared__ __align__(16) uint32_t Bh[64 * 24];   // words [n][kslot] stride 24
    __shared__ __align__(16) uint32_t Bl[64 * 24];

    const int which = blockIdx.y;
    const int m0 = blockIdx.x * 128;
    const int tid = threadIdx.x;
    const int wid = tid >> 5, lane = tid & 31;
    const int lr = lane >> 2, lc = lane & 3;

    const uint32_t AsA = smem_u32(As), BhA = smem_u32(Bh), BlA = smem_u32(Bl);

    float acc[2][8][4];
#pragma unroll
    for (int mt = 0; mt < 2; mt++)
#pragma unroll
        for (int nt = 0; nt < 8; nt++)
#pragma unroll
            for (int i = 0; i < 4; i++) acc[mt][nt][i] = 0.f;

    for (int kt = 0; kt < Cn / 32; kt++) {
        // A fill: 128 rows x 8 chunks (32 fp32 = 128B) = 1024 chunks
#pragma unroll
        for (int l = 0; l < 8; l++) {
            int idx = tid + l * 128;
            int row = idx >> 3, ch = idx & 7;
            CP16(AsA + row * 160 + ch * 16,
                 x + (size_t)(m0 + row) * Cn + kt * 32 + ch * 4);
        }
        // B fill: Bh/Bl 64 rows x 4 chunks (16 words = 64B) each = 512 chunks total
        const size_t tb = (size_t)(which * 32 + kt) * 1024;
#pragma unroll
        for (int l = 0; l < 4; l++) {
            int idx = tid + l * 128;          // 0..511
            int sel = idx >> 8;               // 0: Bh, 1: Bl
            int r = idx & 255;
            int n = r >> 2, ch = r & 3;
            uint32_t dst = (sel ? BlA : BhA) + n * 96 + ch * 16;
            const uint32_t* src = (sel ? g_wlo : g_whi) + tb + n * 16 + ch * 4;
            CP16(dst, src);
        }
        CP_COMMIT();
        CP_WAIT0();
        __syncthreads();

#pragma unroll
        for (int c = 0; c < 2; c++) {         // two k16 chunks
            uint32_t ah[2][4], al[2][4];
#pragma unroll
            for (int mt = 0; mt < 2; mt++) {
                int rb = wid * 32 + mt * 16 + lr;
                float2 p0 = *(const float2*)&As[rb * 40 + c * 16 + 2 * lc];
                float2 p1 = *(const float2*)&As[(rb + 8) * 40 + c * 16 + 2 * lc];
                float2 p2 = *(const float2*)&As[rb * 40 + c * 16 + 8 + 2 * lc];
                float2 p3 = *(const float2*)&As[(rb + 8) * 40 + c * 16 + 8 + 2 * lc];
                spb2(p0.x, p0.y, ah[mt][0], al[mt][0]);
                spb2(p1.x, p1.y, ah[mt][1], al[mt][1]);
                spb2(p2.x, p2.y, ah[mt][2], al[mt][2]);
                spb2(p3.x, p3.y, ah[mt][3], al[mt][3]);
            }
#pragma unroll
            for (int nt = 0; nt < 8; nt++) {
                uint2 bh = *(const uint2*)&Bh[(nt * 8 + lr) * 24 + c * 8 + 2 * lc];
                uint2 bl = *(const uint2*)&Bl[(nt * 8 + lr) * 24 + c * 8 + 2 * lc];
#pragma unroll
                for (int mt = 0; mt < 2; mt++) {
                    mmab(acc[mt][nt], ah[mt][0], ah[mt][1], ah[mt][2], ah[mt][3], bh.x, bh.y);
                    mmab(acc[mt][nt], ah[mt][0], ah[mt][1], ah[mt][2], ah[mt][3], bl.x, bl.y);
                    mmab(acc[mt][nt], al[mt][0], al[mt][1], al[mt][2], al[mt][3], bh.x, bh.y);
                }
            }
        }
        __syncthreads();
    }

    // Epilogue: pre-split / pre-pack by output kind
#pragma unroll
    for (int mt = 0; mt < 2; mt++)
#pragma unroll
        for (int rr = 0; rr < 2; rr++) {
            int row = m0 + wid * 32 + mt * 16 + rr * 8 + lr;
#pragma unroll
            for (int nt = 0; nt < 8; nt++) {
                float v0 = acc[mt][nt][rr * 2 + 0];
                float v1 = acc[mt][nt][rr * 2 + 1];
                int col0 = nt * 8 + 2 * lc;
                int sl = kslot(nt * 4 + lc);
                if (which == 0) {
                    uint32_t hw, lw;
                    spb2(v0 * 0.125f, v1 * 0.125f, hw, lw);
                    g_qhi[(size_t)row * 32 + sl] = hw;
                    g_qlo[(size_t)row * 32 + sl] = lw;
                } else if (which == 1) {
                    uint32_t hw, lw;
                    spb2(v0, v1, hw, lw);
                    g_khi[(size_t)row * 32 + sl] = hw;
                    g_klo[(size_t)row * 32 + sl] = lw;
                } else {
                    int bb = row >> 11, t = row & 2047;
                    int ep = eperm(t);
                    unsigned short h0 = b16(v0);
                    unsigned short l0 = b16(v0 - fb16(h0));
                    unsigned short h1 = b16(v1);
                    unsigned short l1 = b16(v1 - fb16(h1));
                    g_vhiT[(size_t)(bb * Hn + col0) * Tn + ep] = h0;
                    g_vloT[(size_t)(bb * Hn + col0) * Tn + ep] = l0;
                    g_vhiT[(size_t)(bb * Hn + col0 + 1) * Tn + ep] = h1;
                    g_vloT[(size_t)(bb * Hn + col0 + 1) * Tn + ep] = l1;
                }
            }
        }
}

// ================= Kernel 2: flash attention (bf16 3-split) =================
// grid 512 (heavy-first), block 128 (4 warps, each m16 x n64).
// Q_TILE=64, KV_TILE=64. Static SMEM 40960B -> 4 CTAs/SM.
__global__ __launch_bounds__(128, 4) void attn_kernel(float* __restrict__ out)
{
    __shared__ __align__(16) uint32_t Kh[64 * 40];   // [s][kslot(h/2)] stride 40
    __shared__ __align__(16) uint32_t Kl[64 * 40];
    __shared__ __align__(16) uint32_t Vh[64 * 40];   // [h][kslot(s/2)]
    __shared__ __align__(16) uint32_t Vl[64 * 40];
    uint32_t* Ph = Kh;                               // P overlay [q][kslot(s/2)]
    uint32_t* Pl = Kl;

    const int qt = 31 - (blockIdx.x >> 4);
    const int b  = blockIdx.x & 15;
    const int q0 = qt * 64;
    const size_t bT = (size_t)b * Tn;
    const int tid = threadIdx.x;
    const int wid = tid >> 5, lane = tid & 31;
    const int lr = lane >> 2, lc = lane & 3;
    const int r0l = wid * 16 + lr, r1l = r0l + 8;

    const uint32_t KhA = smem_u32(Kh), KlA = smem_u32(Kl);
    const uint32_t VhA = smem_u32(Vh), VlA = smem_u32(Vl);

    // Q fragments: pre-split, pre-packed words straight from global
    uint32_t qah[4][4], qal[4][4];
#pragma unroll
    for (int c = 0; c < 4; c++) {
        uint2 h0 = *(const uint2*)&g_qhi[(bT + q0 + r0l) * 32 + c * 8 + 2 * lc];
        uint2 h1 = *(const uint2*)&g_qhi[(bT + q0 + r1l) * 32 + c * 8 + 2 * lc];
        uint2 l0 = *(const uint2*)&g_qlo[(bT + q0 + r0l) * 32 + c * 8 + 2 * lc];
        uint2 l1 = *(const uint2*)&g_qlo[(bT + q0 + r1l) * 32 + c * 8 + 2 * lc];
        qah[c][0] = h0.x; qah[c][1] = h1.x; qah[c][2] = h0.y; qah[c][3] = h1.y;
        qal[c][0] = l0.x; qal[c][1] = l1.x; qal[c][2] = l0.y; qal[c][3] = l1.y;
    }

    float o[8][4];
    float mrow[2] = { -1e30f, -1e30f };
    float lrow[2] = { 0.f, 0.f };
#pragma unroll
    for (int nt = 0; nt < 8; nt++)
#pragma unroll
        for (int i = 0; i < 4; i++) o[nt][i] = 0.f;

    for (int st = 0; st <= qt; st++) {
        const int s0 = st * 64;
        __syncthreads();  // previous iteration fully consumed

        // cp.async fill: warp w owns array w. 64 rows x 8 chunks = 512 chunks -> 16/lane.
#pragma unroll
        for (int i = 0; i < 16; i++) {
            int c = lane + i * 32;        // 0..511
            int row = c >> 3, ch = c & 7;
            if (wid == 0)
                CP16(KhA + row * 160 + ch * 16,
                     g_khi + (bT + s0 + row) * 32 + ch * 4);
            else if (wid == 1)
                CP16(KlA + row * 160 + ch * 16,
                     g_klo + (bT + s0 + row) * 32 + ch * 4);
            else if (wid == 2)
                CP16(VhA + row * 160 + ch * 16,
                     g_vhiT + (size_t)(b * Hn + row) * Tn + s0 + ch * 8);
            else
                CP16(VlA + row * 160 + ch * 16,
                     g_vloT + (size_t)(b * Hn + row) * Tn + s0 + ch * 8);
        }
        CP_COMMIT();
        CP_WAIT0();
        __syncthreads();

        // ---- S = Q K^T ----
        float sacc[8][4];
#pragma unroll
        for (int nt = 0; nt < 8; nt++)
#pragma unroll
            for (int i = 0; i < 4; i++) sacc[nt][i] = 0.f;

#pragma unroll
        for (int c = 0; c < 4; c++) {
#pragma unroll
            for (int nt = 0; nt < 8; nt++) {
                uint2 bh = *(const uint2*)&Kh[(nt * 8 + lr) * 40 + c * 8 + 2 * lc];
                uint2 bl = *(const uint2*)&Kl[(nt * 8 + lr) * 40 + c * 8 + 2 * lc];
                mmab(sacc[nt], qah[c][0], qah[c][1], qah[c][2], qah[c][3], bh.x, bh.y);
                mmab(sacc[nt], qah[c][0], qah[c][1], qah[c][2], qah[c][3], bl.x, bl.y);
                mmab(sacc[nt], qal[c][0], qal[c][1], qal[c][2], qal[c][3], bh.x, bh.y);
            }
        }

        if (st == qt) {  // diagonal tile causal mask
            int r0g = q0 + r0l, r1g = q0 + r1l;
#pragma unroll
            for (int nt = 0; nt < 8; nt++) {
                int cg = s0 + nt * 8 + 2 * lc;
                if (cg > r0g)     sacc[nt][0] = -1e30f;
                if (cg + 1 > r0g) sacc[nt][1] = -1e30f;
                if (cg > r1g)     sacc[nt][2] = -1e30f;
                if (cg + 1 > r1g) sacc[nt][3] = -1e30f;
            }
        }

        // ---- online softmax ----
        float mx0 = -1e30f, mx1 = -1e30f;
#pragma unroll
        for (int nt = 0; nt < 8; nt++) {
            mx0 = fmaxf(mx0, fmaxf(sacc[nt][0], sacc[nt][1]));
            mx1 = fmaxf(mx1, fmaxf(sacc[nt][2], sacc[nt][3]));
        }
        mx0 = fmaxf(mx0, __shfl_xor_sync(0xffffffffu, mx0, 1));
        mx0 = fmaxf(mx0, __shfl_xor_sync(0xffffffffu, mx0, 2));
        mx1 = fmaxf(mx1, __shfl_xor_sync(0xffffffffu, mx1, 1));
        mx1 = fmaxf(mx1, __shfl_xor_sync(0xffffffffu, mx1, 2));

        float mn0 = fmaxf(mrow[0], mx0), mn1 = fmaxf(mrow[1], mx1);
        float f0 = __expf(mrow[0] - mn0), f1 = __expf(mrow[1] - mn1);
        mrow[0] = mn0; mrow[1] = mn1;

        float sum0 = 0.f, sum1 = 0.f;
#pragma unroll
        for (int nt = 0; nt < 8; nt++) {
            sacc[nt][0] = __expf(sacc[nt][0] - mn0);
            sacc[nt][1] = __expf(sacc[nt][1] - mn0);
            sacc[nt][2] = __expf(sacc[nt][2] - mn1);
            sacc[nt][3] = __expf(sacc[nt][3] - mn1);
            sum0 += sacc[nt][0] + sacc[nt][1];
            sum1 += sacc[nt][2] + sacc[nt][3];
        }
        sum0 += __shfl_xor_sync(0xffffffffu, sum0, 1);
        sum0 += __shfl_xor_sync(0xffffffffu, sum0, 2);
        sum1 += __shfl_xor_sync(0xffffffffu, sum1, 1);
        sum1 += __shfl_xor_sync(0xffffffffu, sum1, 2);
        lrow[0] = lrow[0] * f0 + sum0;
        lrow[1] = lrow[1] * f1 + sum1;

#pragma unroll
        for (int nt = 0; nt < 8; nt++) {
            o[nt][0] *= f0; o[nt][1] *= f0;
            o[nt][2] *= f1; o[nt][3] *= f1;
        }

        __syncthreads();  // K reads done before P overlay

        // ---- write P as bf16 hi/lo words ----
#pragma unroll
        for (int nt = 0; nt < 8; nt++) {
            int sl = kslot(nt * 4 + lc);
            uint32_t hw, lw;
            spb2(sacc[nt][0], sacc[nt][1], hw, lw);
            Ph[r0l * 40 + sl] = hw;
            Pl[r0l * 40 + sl] = lw;
            spb2(sacc[nt][2], sacc[nt][3], hw, lw);
            Ph[r1l * 40 + sl] = hw;
            Pl[r1l * 40 + sl] = lw;
        }
        __syncwarp();  // PV reads only this warp's rows

        // ---- O += P V ----
#pragma unroll
        for (int c = 0; c < 4; c++) {
            uint2 ph0 = *(const uint2*)&Ph[r0l * 40 + c * 8 + 2 * lc];
            uint2 ph1 = *(const uint2*)&Ph[r1l * 40 + c * 8 + 2 * lc];
            uint2 pl0 = *(const uint2*)&Pl[r0l * 40 + c * 8 + 2 * lc];
            uint2 pl1 = *(const uint2*)&Pl[r1l * 40 + c * 8 + 2 * lc];
#pragma unroll
            for (int nt = 0; nt < 8; nt++) {
                uint2 vh = *(const uint2*)&Vh[(nt * 8 + lr) * 40 + c * 8 + 2 * lc];
                uint2 vl = *(const uint2*)&Vl[(nt * 8 + lr) * 40 + c * 8 + 2 * lc];
                mmab(o[nt], ph0.x, ph1.x, ph0.y, ph1.y, vh.x, vh.y);
                mmab(o[nt], ph0.x, ph1.x, ph0.y, ph1.y, vl.x, vl.y);
                mmab(o[nt], pl0.x, pl1.x, pl0.y, pl1.y, vh.x, vh.y);
            }
        }
    }

    float inv0 = 1.0f / lrow[0], inv1 = 1.0f / lrow[1];
#pragma unroll
    for (int nt = 0; nt < 8; nt++) {
        int col = nt * 8 + 2 * lc;
        *(float2*)&out[(bT + q0 + r0l) * Hn + col] =
            make_float2(o[nt][0] * inv0, o[nt][1] * inv0);
        *(float2*)&out[(bT + q0 + r1l) * Hn + col] =
            make_float2(o[nt][2] * inv1, o[nt][3] * inv1);
    }
}

// ================= launch =================
extern "C" void kernel_launch(void* const* d_in, const int* in_sizes, int n_in,
                              void* d_out, int out_size)
{
    const float* x  = (const float*)d_in[0];
    const float* wq = (const float*)d_in[1];
    const float* wk = (const float*)d_in[2];
    const float* wv = (const float*)d_in[3];
    float* out = (float*)d_out;

    wsplit_kernel<<<dim3(32, 3), 256>>>(wq, wk, wv);
    qkv_kernel<<<dim3((Bn * Tn) / 128, 3), 128>>>(x);
    attn_kernel<<<512, 128>>>(out);
}